// round 11
// baseline (speedup 1.0000x reference)
#include <cuda_runtime.h>
#include <cstdint>
#include <math.h>

#define E_TOT  800000
#define HALF_E 400000
#define TPB    256
#define EPB    512   // elements per block (2 per thread)

// material id per element. Identity: block1 (lam,mu) = 2x block0, H linear in
// (mu_eff, lam) => H(mat1) = 2*H(mat0). Compute with (lam=1, mu=0.5), scale
// vol by (1 + matid).
__device__ unsigned char g_matid[E_TOT];

__global__ void mark_b1_kernel(const int* __restrict__ b1) {
    int i = blockIdx.x * blockDim.x + threadIdx.x;
    if (i < HALF_E / 4) {
        int4 b = reinterpret_cast<const int4*>(b1)[i];
        g_matid[b.x] = 1;
        g_matid[b.y] = 1;
        g_matid[b.z] = 1;
        g_matid[b.w] = 1;
    }
}

__device__ __forceinline__ void compute_elem(
    float2 g0, float2 g1, float2 g2,
    float2 u0, float2 u1, float2 u2,
    float vol, float mu_eff, float* row /* smem, 36 floats, 16B aligned */)
{
    float G00 = u0.x * g0.x + u1.x * g1.x + u2.x * g2.x;
    float G01 = u0.x * g0.y + u1.x * g1.y + u2.x * g2.y;
    float G10 = u0.y * g0.x + u1.y * g1.x + u2.y * g2.x;
    float G11 = u0.y * g0.y + u1.y * g1.y + u2.y * g2.y;

    float F00 = 1.0f + G00, F01 = G01;
    float F10 = G10,        F11 = 1.0f + G11;

    float J    = F00 * F11 - F01 * F10;
    float logJ = __logf(J);
    float invJ = __frcp_rn(J);

    float i00 =  F11 * invJ, i01 = -F01 * invJ;
    float i10 = -F10 * invJ, i11 =  F00 * invJ;

    float ga[3][2] = { {g0.x, g0.y}, {g1.x, g1.y}, {g2.x, g2.y} };

    float h[3][2];
#pragma unroll
    for (int a = 0; a < 3; a++) {
        h[a][0] = ga[a][0] * i00 + ga[a][1] * i10;
        h[a][1] = ga[a][0] * i01 + ga[a][1] * i11;
    }

    const float cgeo = mu_eff - logJ;   // lam = 1

    float o[36];
#pragma unroll
    for (int a = 0; a < 3; a++) {
#pragma unroll
        for (int b = 0; b < 3; b++) {
            float gg = ga[a][0] * ga[b][0] + ga[a][1] * ga[b][1];
#pragma unroll
            for (int i = 0; i < 2; i++) {
#pragma unroll
                for (int j = 0; j < 2; j++) {
                    float v = cgeo * h[a][j] * h[b][i] + h[a][i] * h[b][j];
                    if (i == j) v += mu_eff * gg;
                    o[((a * 2 + i) * 3 + b) * 2 + j] = v * vol;
                }
            }
        }
    }

    float4* r4 = reinterpret_cast<float4*>(row);
#pragma unroll
    for (int k = 0; k < 9; k++)
        r4[k] = make_float4(o[4 * k + 0], o[4 * k + 1], o[4 * k + 2], o[4 * k + 3]);
}

__global__ void __launch_bounds__(TPB)
hess_kernel(const float* __restrict__ U,        // [N,2]
            const float* __restrict__ state,    // [E,1,1]
            const int*   __restrict__ conns,    // [E,3]
            const float* __restrict__ sg,       // [E,1,3,2]
            const float* __restrict__ vols,     // [E,1]
            float*       __restrict__ out)      // [E,3,2,3,2]
{
    // Separate regions: inputs persist across both element phases.
    __shared__ __align__(16) float s_in[EPB * 9];    // sg: EPB*6, conns: EPB*3 -> 18KB
    __shared__ __align__(16) float s_out[TPB * 36];  // 36KB output staging

    const int tid  = threadIdx.x;
    const int blk  = blockIdx.x;
    const int base = blk * EPB;
    const int lim  = min(EPB, E_TOT - base);          // 512, or 256 in last block
    const bool has2 = (lim == EPB);                   // uniform per block

    // ---- cooperative coalesced staging (guarded for the partial last block)
    {
        float2* s_sg = reinterpret_cast<float2*>(s_in);
        const float2* sgb = reinterpret_cast<const float2*>(sg + (size_t)base * 6);
        const int n2 = lim * 3;
#pragma unroll
        for (int it = 0; it < 6; it++) {
            int idx = it * TPB + tid;
            if (idx < n2) s_sg[idx] = sgb[idx];
        }
        int* s_cn = reinterpret_cast<int*>(s_in + EPB * 6);
        const int* cb = conns + (size_t)base * 3;
        const int ni = lim * 3;
#pragma unroll
        for (int it = 0; it < 6; it++) {
            int idx = it * TPB + tid;
            if (idx < ni) s_cn[idx] = cb[idx];
        }
    }
    __syncthreads();

    const int* s_cn = reinterpret_cast<const int*>(s_in + EPB * 6);
    const float2* U2 = reinterpret_cast<const float2*>(U);

    // ---- issue ALL 6 random gathers (both elements) for max MLP
    int a0 = s_cn[tid * 3 + 0];
    int a1 = s_cn[tid * 3 + 1];
    int a2 = s_cn[tid * 3 + 2];
    float2 ua0 = __ldg(&U2[a0]);
    float2 ua1 = __ldg(&U2[a1]);
    float2 ua2 = __ldg(&U2[a2]);

    float2 ub0, ub1, ub2;
    if (has2) {
        int b0i = s_cn[(TPB + tid) * 3 + 0];
        int b1i = s_cn[(TPB + tid) * 3 + 1];
        int b2i = s_cn[(TPB + tid) * 3 + 2];
        ub0 = __ldg(&U2[b0i]);
        ub1 = __ldg(&U2[b1i]);
        ub2 = __ldg(&U2[b2i]);
    }

    // scalar per-element data
    const int e0 = base + tid;
    float vol0 = __ldg(&vols[e0]) * (float)(1 + g_matid[e0]);
    float mue0 = 0.5f + 0.005f * __ldg(&state[e0]);
    float vol1 = 0.0f, mue1 = 0.0f;
    if (has2) {
        const int e1 = e0 + TPB;
        vol1 = __ldg(&vols[e1]) * (float)(1 + g_matid[e1]);
        mue1 = 0.5f + 0.005f * __ldg(&state[e1]);
    }

    // ---- phase 0: element tid
    {
        const float2* p = reinterpret_cast<const float2*>(s_in + tid * 6);
        float2 g0 = p[0], g1 = p[1], g2 = p[2];
        compute_elem(g0, g1, g2, ua0, ua1, ua2, vol0, mue0, s_out + tid * 36);
    }
    __syncthreads();
    {
        const float4* s4 = reinterpret_cast<const float4*>(s_out);
        float4* o4 = reinterpret_cast<float4*>(out) + (size_t)base * 9;
#pragma unroll
        for (int it = 0; it < 9; it++)
            o4[it * TPB + tid] = s4[it * TPB + tid];
    }

    // ---- phase 1: element tid + 256 (skipped uniformly in last block)
    if (has2) {
        __syncthreads();
        {
            const float2* p = reinterpret_cast<const float2*>(s_in + (TPB + tid) * 6);
            float2 g0 = p[0], g1 = p[1], g2 = p[2];
            compute_elem(g0, g1, g2, ub0, ub1, ub2, vol1, mue1, s_out + tid * 36);
        }
        __syncthreads();
        {
            const float4* s4 = reinterpret_cast<const float4*>(s_out);
            float4* o4 = reinterpret_cast<float4*>(out) + ((size_t)base + TPB) * 9;
#pragma unroll
            for (int it = 0; it < 9; it++)
                o4[it * TPB + tid] = s4[it * TPB + tid];
        }
    }
}

extern "C" void kernel_launch(void* const* d_in, const int* in_sizes, int n_in,
                              void* d_out, int out_size) {
    // metadata order: U, coords, state, conns, shapes, shapeGrads, vols, blocks0, blocks1
    const float* U      = (const float*)d_in[0];
    const float* state  = (const float*)d_in[2];
    const int*   conns  = (const int*)  d_in[3];
    const float* sg     = (const float*)d_in[5];
    const float* vols   = (const float*)d_in[6];
    const int*   b1     = (const int*)  d_in[8];
    float* out = (float*)d_out;

    void* matid_ptr = nullptr;
    cudaGetSymbolAddress(&matid_ptr, g_matid);
    cudaMemsetAsync(matid_ptr, 0, E_TOT);

    mark_b1_kernel<<<(HALF_E / 4 + TPB - 1) / TPB, TPB>>>(b1);

    hess_kernel<<<(E_TOT + EPB - 1) / EPB, TPB>>>(U, state, conns, sg, vols, out);
}

// round 12
// speedup vs baseline: 1.2564x; 1.2564x over previous
#include <cuda_runtime.h>
#include <cstdint>
#include <math.h>

#define E_TOT  800000
#define HALF_E 400000
#define TPB    256

// material id per element. Identity: block1 (lam,mu) = 2x block0, H linear in
// (mu_eff, lam) => H(mat1) = 2*H(mat0). Compute with (lam=1, mu=0.5), scale
// vol by (1 + matid).
__device__ unsigned char g_matid[E_TOT];

// single prologue kernel: blocks0/blocks1 are disjoint and cover all E, so
// scattering 0s and 1s fully (re)initializes g_matid — no memset node needed.
__global__ void mark_both_kernel(const int* __restrict__ b0,
                                 const int* __restrict__ b1) {
    int i = blockIdx.x * blockDim.x + threadIdx.x;
    if (i < HALF_E / 4) {
        int4 a = reinterpret_cast<const int4*>(b0)[i];
        int4 b = reinterpret_cast<const int4*>(b1)[i];
        g_matid[a.x] = 0; g_matid[a.y] = 0; g_matid[a.z] = 0; g_matid[a.w] = 0;
        g_matid[b.x] = 1; g_matid[b.y] = 1; g_matid[b.z] = 1; g_matid[b.w] = 1;
    }
}

__global__ void __launch_bounds__(TPB)
hess_kernel(const float* __restrict__ U,        // [N,2]
            const float* __restrict__ state,    // [E,1,1]
            const int*   __restrict__ conns,    // [E,3]
            const float* __restrict__ sg,       // [E,1,3,2]
            const float* __restrict__ vols,     // [E,1]
            float*       __restrict__ out)      // [E,3,2,3,2]
{
    // Separate input/output regions: only TWO barriers needed
    // (post-staging, post-output-staging). 45KB total -> 5 CTAs/SM.
    __shared__ __align__(16) float s_in[TPB * 9];    // sg 6f + conns 3i per elem
    __shared__ __align__(16) float s_out[TPB * 36];  // stride-36 output staging

    const int tid = threadIdx.x;
    const int blk = blockIdx.x;
    const int e   = blk * TPB + tid;          // grid exact: 3125*256 = 800000

    // ---- cooperative coalesced staging (read-once: evict-first hint)
    {
        float2* s2 = reinterpret_cast<float2*>(s_in);
        const float2* sgb = reinterpret_cast<const float2*>(sg + (size_t)blk * (TPB * 6));
#pragma unroll
        for (int it = 0; it < 3; it++)
            s2[it * TPB + tid] = __ldcs(&sgb[it * TPB + tid]);
        int* conn_s = reinterpret_cast<int*>(s_in + 6 * TPB);
        const int* cb = conns + (size_t)blk * (TPB * 3);
#pragma unroll
        for (int it = 0; it < 3; it++)
            conn_s[it * TPB + tid] = __ldcs(&cb[it * TPB + tid]);
    }
    __syncthreads();

    float2 g0, g1, g2;
    {
        const float2* p = reinterpret_cast<const float2*>(s_in + tid * 6);
        g0 = p[0]; g1 = p[1]; g2 = p[2];
    }
    int c0, c1, c2;
    {
        const int* conn_s = reinterpret_cast<const int*>(s_in + 6 * TPB);
        c0 = conn_s[tid * 3 + 0];
        c1 = conn_s[tid * 3 + 1];
        c2 = conn_s[tid * 3 + 2];
    }

    float vol = __ldcs(&vols[e]);
    float Q   = __ldcs(&state[e]);
    int   m   = g_matid[e];

    vol *= (float)(1 + m);                    // material fold
    const float mu_eff = 0.5f + 0.005f * Q;   // mu0*(1+0.01Q), mu0=0.5; lam0=1

    // ---- gather nodal displacements (keep default caching: L2-resident)
    const float2* U2 = reinterpret_cast<const float2*>(U);
    float2 u0 = __ldg(&U2[c0]);
    float2 u1 = __ldg(&U2[c1]);
    float2 u2 = __ldg(&U2[c2]);

    // gradU[c][d] = sum_n U[n][c] * g[n][d]
    float G00 = u0.x * g0.x + u1.x * g1.x + u2.x * g2.x;
    float G01 = u0.x * g0.y + u1.x * g1.y + u2.x * g2.y;
    float G10 = u0.y * g0.x + u1.y * g1.x + u2.y * g2.x;
    float G11 = u0.y * g0.y + u1.y * g1.y + u2.y * g2.y;

    float F00 = 1.0f + G00, F01 = G01;
    float F10 = G10,        F11 = 1.0f + G11;

    float J    = F00 * F11 - F01 * F10;
    float logJ = __logf(J);
    float invJ = __frcp_rn(J);

    float i00 =  F11 * invJ, i01 = -F01 * invJ;
    float i10 = -F10 * invJ, i11 =  F00 * invJ;

    float ga[3][2] = { {g0.x, g0.y}, {g1.x, g1.y}, {g2.x, g2.y} };

    float h[3][2];
#pragma unroll
    for (int a = 0; a < 3; a++) {
        h[a][0] = ga[a][0] * i00 + ga[a][1] * i10;
        h[a][1] = ga[a][0] * i01 + ga[a][1] * i11;
    }

    const float cgeo = mu_eff - logJ;   // lam = 1

    // H[a,i,b,j] = vol*( mu_eff*delta_ij*(g_a.g_b) + cgeo*h_a[j]h_b[i] + h_a[i]h_b[j] )
    float o[36];
#pragma unroll
    for (int a = 0; a < 3; a++) {
#pragma unroll
        for (int b = 0; b < 3; b++) {
            float gg = ga[a][0] * ga[b][0] + ga[a][1] * ga[b][1];
#pragma unroll
            for (int i = 0; i < 2; i++) {
#pragma unroll
                for (int j = 0; j < 2; j++) {
                    float v = cgeo * h[a][j] * h[b][i] + h[a][i] * h[b][j];
                    if (i == j) v += mu_eff * gg;
                    o[((a * 2 + i) * 3 + b) * 2 + j] = v * vol;
                }
            }
        }
    }

    // stage element-contiguous (stride 36 floats), 9x STS.128
    {
        float4* row = reinterpret_cast<float4*>(s_out + tid * 36);
#pragma unroll
        for (int k = 0; k < 9; k++)
            row[k] = make_float4(o[4 * k + 0], o[4 * k + 1], o[4 * k + 2], o[4 * k + 3]);
    }

    __syncthreads();

    // linear copy-out: LDS.128 + STG.128 streaming (evict-first: keep U in L2)
    {
        const float4* s4 = reinterpret_cast<const float4*>(s_out);
        float4* o4 = reinterpret_cast<float4*>(out) + (size_t)blk * (TPB * 9);
#pragma unroll
        for (int it = 0; it < 9; it++)
            __stcs(&o4[it * TPB + tid], s4[it * TPB + tid]);
    }
}

extern "C" void kernel_launch(void* const* d_in, const int* in_sizes, int n_in,
                              void* d_out, int out_size) {
    // metadata order: U, coords, state, conns, shapes, shapeGrads, vols, blocks0, blocks1
    const float* U      = (const float*)d_in[0];
    const float* state  = (const float*)d_in[2];
    const int*   conns  = (const int*)  d_in[3];
    const float* sg     = (const float*)d_in[5];
    const float* vols   = (const float*)d_in[6];
    const int*   b0     = (const int*)  d_in[7];
    const int*   b1     = (const int*)  d_in[8];
    float* out = (float*)d_out;

    mark_both_kernel<<<(HALF_E / 4 + TPB - 1) / TPB, TPB>>>(b0, b1);

    hess_kernel<<<E_TOT / TPB, TPB>>>(U, state, conns, sg, vols, out);
}

// round 13
// speedup vs baseline: 1.4602x; 1.1622x over previous
#include <cuda_runtime.h>
#include <cstdint>
#include <math.h>

#define E_TOT  800000
#define HALF_E 400000
#define TPB    256

// material id per element. Identity: block1 (lam,mu) = 2x block0, H linear in
// (mu_eff, lam) => H(mat1) = 2*H(mat0). Compute with (lam=1, mu=0.5), scale
// vol by (1 + matid).
__device__ unsigned char g_matid[E_TOT];

// scatter ones for block1 only (zeroing via cudaMemsetAsync); 4x ILP
__global__ void mark_b1_kernel(const int* __restrict__ b1) {
    int i = blockIdx.x * blockDim.x + threadIdx.x;
    if (i < HALF_E / 4) {
        int4 b = reinterpret_cast<const int4*>(b1)[i];
        g_matid[b.x] = 1;
        g_matid[b.y] = 1;
        g_matid[b.z] = 1;
        g_matid[b.w] = 1;
    }
}

__global__ void __launch_bounds__(TPB)
hess_kernel(const float* __restrict__ U,        // [N,2]
            const float* __restrict__ state,    // [E,1,1]
            const int*   __restrict__ conns,    // [E,3]
            const float* __restrict__ sg,       // [E,1,3,2]
            const float* __restrict__ vols,     // [E,1]
            float*       __restrict__ out)      // [E,3,2,3,2]
{
    // Buffer reused: staged inputs first, then staged outputs
    // (element-contiguous, stride 36 floats = 144B, 16B aligned).
    __shared__ __align__(16) float smem[TPB * 36];

    const int tid = threadIdx.x;
    const int blk = blockIdx.x;
    const int e   = blk * TPB + tid;          // grid exact: 3125*256 = 800000

    // ---- cooperative coalesced staging, float4-wide.
    // sg chunk: TPB*6 floats = 384 float4; conns chunk: TPB*3 ints = 192 int4.
    // Linear layout in smem (same as gmem chunk order).
    {
        float4* s4 = reinterpret_cast<float4*>(smem);
        const float4* sgb = reinterpret_cast<const float4*>(sg + (size_t)blk * (TPB * 6));
        s4[tid] = sgb[tid];
        if (tid < 128) s4[256 + tid] = sgb[256 + tid];
        int4* c4 = reinterpret_cast<int4*>(smem + 6 * TPB);
        const int4* cb = reinterpret_cast<const int4*>(conns + (size_t)blk * (TPB * 3));
        if (tid < 192) c4[tid] = cb[tid];
    }
    __syncthreads();

    // per-thread reads from smem
    float2 g0, g1, g2;
    {
        const float2* p = reinterpret_cast<const float2*>(smem + tid * 6);
        g0 = p[0]; g1 = p[1]; g2 = p[2];
    }
    int c0, c1, c2;
    {
        const int* conn_s = reinterpret_cast<const int*>(smem + 6 * TPB);
        c0 = conn_s[tid * 3 + 0];
        c1 = conn_s[tid * 3 + 1];
        c2 = conn_s[tid * 3 + 2];
    }

    float vol = __ldg(&vols[e]);
    float Q   = __ldg(&state[e]);
    int   m   = g_matid[e];

    vol *= (float)(1 + m);                    // material fold
    const float mu_eff = 0.5f + 0.005f * Q;   // mu0*(1+0.01Q), mu0=0.5; lam0=1

    // ---- gather nodal displacements (L2-resident table) ----
    const float2* U2 = reinterpret_cast<const float2*>(U);
    float2 u0 = __ldg(&U2[c0]);
    float2 u1 = __ldg(&U2[c1]);
    float2 u2 = __ldg(&U2[c2]);

    __syncthreads();   // staged inputs consumed; buffer reusable for output

    // gradU[c][d] = sum_n U[n][c] * g[n][d]
    float G00 = u0.x * g0.x + u1.x * g1.x + u2.x * g2.x;
    float G01 = u0.x * g0.y + u1.x * g1.y + u2.x * g2.y;
    float G10 = u0.y * g0.x + u1.y * g1.x + u2.y * g2.x;
    float G11 = u0.y * g0.y + u1.y * g1.y + u2.y * g2.y;

    float F00 = 1.0f + G00, F01 = G01;
    float F10 = G10,        F11 = 1.0f + G11;

    float J    = F00 * F11 - F01 * F10;
    float logJ = __logf(J);
    float invJ = __frcp_rn(J);

    float i00 =  F11 * invJ, i01 = -F01 * invJ;
    float i10 = -F10 * invJ, i11 =  F00 * invJ;

    float ga[3][2] = { {g0.x, g0.y}, {g1.x, g1.y}, {g2.x, g2.y} };

    float h[3][2];
#pragma unroll
    for (int a = 0; a < 3; a++) {
        h[a][0] = ga[a][0] * i00 + ga[a][1] * i10;
        h[a][1] = ga[a][0] * i01 + ga[a][1] * i11;
    }

    const float cgeo = mu_eff - logJ;   // lam = 1

    // H[a,i,b,j] = vol*( mu_eff*delta_ij*(g_a.g_b) + cgeo*h_a[j]h_b[i] + h_a[i]h_b[j] )
    float o[36];
#pragma unroll
    for (int a = 0; a < 3; a++) {
#pragma unroll
        for (int b = 0; b < 3; b++) {
            float gg = ga[a][0] * ga[b][0] + ga[a][1] * ga[b][1];
#pragma unroll
            for (int i = 0; i < 2; i++) {
#pragma unroll
                for (int j = 0; j < 2; j++) {
                    float v = cgeo * h[a][j] * h[b][i] + h[a][i] * h[b][j];
                    if (i == j) v += mu_eff * gg;
                    o[((a * 2 + i) * 3 + b) * 2 + j] = v * vol;
                }
            }
        }
    }

    // stage element-contiguous (stride 36 floats), 9x STS.128 conflict-free
    {
        float4* row = reinterpret_cast<float4*>(smem + tid * 36);
#pragma unroll
        for (int k = 0; k < 9; k++)
            row[k] = make_float4(o[4 * k + 0], o[4 * k + 1], o[4 * k + 2], o[4 * k + 3]);
    }

    __syncthreads();

    // linear copy-out: LDS.128 + STG.128 streaming (evict-first keeps U in L2)
    {
        const float4* s4 = reinterpret_cast<const float4*>(smem);
        float4* o4 = reinterpret_cast<float4*>(out) + (size_t)blk * (TPB * 9);
#pragma unroll
        for (int it = 0; it < 9; it++)
            __stcs(&o4[it * TPB + tid], s4[it * TPB + tid]);
    }
}

extern "C" void kernel_launch(void* const* d_in, const int* in_sizes, int n_in,
                              void* d_out, int out_size) {
    // metadata order: U, coords, state, conns, shapes, shapeGrads, vols, blocks0, blocks1
    const float* U      = (const float*)d_in[0];
    const float* state  = (const float*)d_in[2];
    const int*   conns  = (const int*)  d_in[3];
    const float* sg     = (const float*)d_in[5];
    const float* vols   = (const float*)d_in[6];
    const int*   b1     = (const int*)  d_in[8];
    float* out = (float*)d_out;

    void* matid_ptr = nullptr;
    cudaGetSymbolAddress(&matid_ptr, g_matid);
    cudaMemsetAsync(matid_ptr, 0, E_TOT);

    mark_b1_kernel<<<(HALF_E / 4 + TPB - 1) / TPB, TPB>>>(b1);

    hess_kernel<<<E_TOT / TPB, TPB>>>(U, state, conns, sg, vols, out);
}